// round 1
// baseline (speedup 1.0000x reference)
#include <cuda_runtime.h>

// Problem dims (fixed by the dataset)
#define BDIM 512
#define FDIM 1024
#define H1D  512
#define H2D  256
#define OUTD 128
#define KDD  5
#define NMD  (OUTD*KDD)   // 640
#define ZD   (H2D+OUTD)   // 384

// Scratch (device globals — no allocation allowed)
__device__ float g_h1[BDIM*H1D];
__device__ float g_z [BDIM*ZD];    // cols 0..255 = h2, cols 256..383 = o_b
__device__ float g_M [BDIM*NMD];
__device__ float g_z3[BDIM*OUTD];

// ---------------------------------------------------------------------------
// Tiled fp32 GEMM: C[M,N] = act(A[M,K] @ Bm[K,N] + bias)
// 64x64 block tile, 256 threads, 4x4 per-thread micro-tile, TK=16.
// All dims here are multiples of the tile sizes (no bounds checks needed).
// ---------------------------------------------------------------------------
template<int RELU, int BIAS>
__global__ __launch_bounds__(256)
void gemm64(const float* __restrict__ A, const float* __restrict__ Bm,
            const float* __restrict__ bias, float* __restrict__ C,
            int K, int lda, int ldb, int ldc)
{
    __shared__ float As[16][68];   // [k][m], +4 pad keeps float4 alignment
    __shared__ float Bs[16][68];   // [k][n]

    const int tid = threadIdx.x;
    const int tx  = tid & 15;      // n direction
    const int ty  = tid >> 4;      // m direction
    const int row0 = blockIdx.y * 64;
    const int col0 = blockIdx.x * 64;

    float acc[4][4] = {};

    for (int k0 = 0; k0 < K; k0 += 16) {
        // Load A tile (64 rows x 16 k), store transposed As[k][m]
        #pragma unroll
        for (int i = 0; i < 4; i++) {
            int idx = tid + i * 256;
            int m = idx >> 4, kk = idx & 15;
            As[kk][m] = A[(row0 + m) * lda + k0 + kk];
        }
        // Load B tile (16 k x 64 n) — coalesced along n
        #pragma unroll
        for (int i = 0; i < 4; i++) {
            int idx = tid + i * 256;
            int kk = idx >> 6, n = idx & 63;
            Bs[kk][n] = Bm[(k0 + kk) * ldb + col0 + n];
        }
        __syncthreads();

        #pragma unroll
        for (int kk = 0; kk < 16; kk++) {
            float4 a = *(const float4*)&As[kk][ty * 4];
            float4 b = *(const float4*)&Bs[kk][tx * 4];
            acc[0][0] += a.x * b.x; acc[0][1] += a.x * b.y;
            acc[0][2] += a.x * b.z; acc[0][3] += a.x * b.w;
            acc[1][0] += a.y * b.x; acc[1][1] += a.y * b.y;
            acc[1][2] += a.y * b.z; acc[1][3] += a.y * b.w;
            acc[2][0] += a.z * b.x; acc[2][1] += a.z * b.y;
            acc[2][2] += a.z * b.z; acc[2][3] += a.z * b.w;
            acc[3][0] += a.w * b.x; acc[3][1] += a.w * b.y;
            acc[3][2] += a.w * b.z; acc[3][3] += a.w * b.w;
        }
        __syncthreads();
    }

    // Epilogue: bias + leaky-relu, float4 stores
    float4 bv = make_float4(0.f, 0.f, 0.f, 0.f);
    if (BIAS) {
        bv.x = bias[col0 + tx * 4 + 0];
        bv.y = bias[col0 + tx * 4 + 1];
        bv.z = bias[col0 + tx * 4 + 2];
        bv.w = bias[col0 + tx * 4 + 3];
    }
    #pragma unroll
    for (int mi = 0; mi < 4; mi++) {
        float4 v;
        v.x = acc[mi][0] + bv.x;
        v.y = acc[mi][1] + bv.y;
        v.z = acc[mi][2] + bv.z;
        v.w = acc[mi][3] + bv.w;
        if (RELU) {
            v.x = v.x >= 0.f ? v.x : 0.2f * v.x;
            v.y = v.y >= 0.f ? v.y : 0.2f * v.y;
            v.z = v.z >= 0.f ? v.z : 0.2f * v.z;
            v.w = v.w >= 0.f ? v.w : 0.2f * v.w;
        }
        *(float4*)&C[(row0 + ty * 4 + mi) * ldc + col0 + tx * 4] = v;
    }
}

// ---------------------------------------------------------------------------
// Minibatch discrimination:
// o_b[j,o] = sum_i exp(-sum_k |M[i,o,k]-M[j,o,k]|) - 1
// One block per o (128 blocks), 512 threads (one per j).
// The 512x5 slice M[:,o,:] is staged in smem (padded to stride 8 so that the
// first 4 values read as an aligned float4; all lanes read the same i ->
// broadcast, conflict-free).
// ---------------------------------------------------------------------------
__global__ __launch_bounds__(512)
void pairwise_kernel(const float* __restrict__ M, float* __restrict__ z)
{
    __shared__ float s[BDIM * 8];   // 16 KB

    const int o = blockIdx.x;
    const int j = threadIdx.x;

    // Cooperative load of M[:, o, :] (2560 elements)
    for (int idx = j; idx < BDIM * KDD; idx += BDIM) {
        int i = idx / KDD, k = idx - i * KDD;
        s[i * 8 + k] = M[i * NMD + o * KDD + k];
    }
    __syncthreads();

    const float mj0 = s[j * 8 + 0];
    const float mj1 = s[j * 8 + 1];
    const float mj2 = s[j * 8 + 2];
    const float mj3 = s[j * 8 + 3];
    const float mj4 = s[j * 8 + 4];

    float accum = 0.f;
    #pragma unroll 4
    for (int i = 0; i < BDIM; i++) {
        float4 v = *(const float4*)&s[i * 8];
        float  w = s[i * 8 + 4];
        float n = fabsf(v.x - mj0) + fabsf(v.y - mj1) + fabsf(v.z - mj2)
                + fabsf(v.w - mj3) + fabsf(w  - mj4);
        accum += __expf(-n);
    }
    // write into concat buffer column 256+o
    z[j * ZD + H2D + o] = accum - 1.0f;
}

// ---------------------------------------------------------------------------
// Final layer: out[b] = dot(z3[b,:], W4[:,0]) + b4  (one warp per row)
// ---------------------------------------------------------------------------
__global__ __launch_bounds__(256)
void final_kernel(const float* __restrict__ z3, const float* __restrict__ W4,
                  const float* __restrict__ b4, float* __restrict__ out)
{
    int gwarp = (blockIdx.x * blockDim.x + threadIdx.x) >> 5;
    int lane  = threadIdx.x & 31;
    if (gwarp >= BDIM) return;
    float sum = 0.f;
    #pragma unroll
    for (int k = lane; k < OUTD; k += 32)
        sum += z3[gwarp * OUTD + k] * W4[k];
    #pragma unroll
    for (int off = 16; off; off >>= 1)
        sum += __shfl_xor_sync(0xffffffffu, sum, off);
    if (lane == 0) out[gwarp] = sum + b4[0];
}

// ---------------------------------------------------------------------------
extern "C" void kernel_launch(void* const* d_in, const int* in_sizes, int n_in,
                              void* d_out, int out_size)
{
    (void)in_sizes; (void)n_in; (void)out_size;
    const float* x  = (const float*)d_in[0];
    const float* W1 = (const float*)d_in[1];
    const float* b1 = (const float*)d_in[2];
    const float* W2 = (const float*)d_in[3];
    const float* b2 = (const float*)d_in[4];
    const float* T  = (const float*)d_in[5];
    const float* W3 = (const float*)d_in[6];
    const float* b3 = (const float*)d_in[7];
    const float* W4 = (const float*)d_in[8];
    const float* b4 = (const float*)d_in[9];
    float* out = (float*)d_out;

    float *h1, *z, *M, *z3;
    cudaGetSymbolAddress((void**)&h1, g_h1);
    cudaGetSymbolAddress((void**)&z,  g_z);
    cudaGetSymbolAddress((void**)&M,  g_M);
    cudaGetSymbolAddress((void**)&z3, g_z3);

    // h1 = lrelu(x @ W1 + b1)            (512x512, K=1024)
    gemm64<1,1><<<dim3(H1D/64, BDIM/64), 256>>>(x, W1, b1, h1, FDIM, FDIM, H1D, H1D);
    // z[:, :256] = h2 = lrelu(h1 @ W2 + b2)   (512x256, K=512)
    gemm64<1,1><<<dim3(H2D/64, BDIM/64), 256>>>(h1, W2, b2, z, H1D, H1D, H2D, ZD);
    // M = h2 @ T.reshape(256,640)        (512x640, K=256)
    gemm64<0,0><<<dim3(NMD/64, BDIM/64), 256>>>(z, T, nullptr, M, H2D, ZD, NMD, NMD);
    // z[:, 256:] = o_b
    pairwise_kernel<<<OUTD, BDIM>>>(M, z);
    // z3 = lrelu(z @ W3 + b3)            (512x128, K=384)
    gemm64<1,1><<<dim3(OUTD/64, BDIM/64), 256>>>(z, W3, b3, z3, ZD, ZD, OUTD, OUTD);
    // out = z3 @ W4 + b4                 (512x1)
    final_kernel<<<(BDIM*32 + 255)/256, 256>>>(z3, W4, b4, out);
}

// round 3
// speedup vs baseline: 1.0930x; 1.0930x over previous
#include <cuda_runtime.h>

#define BDIM 512
#define FDIM 1024
#define H1D  512
#define H2D  256
#define OUTD 128
#define KDD  5
#define NMD  (OUTD*KDD)   // 640
#define LOG2E 1.44269504f

// Split-K partial buffers (device globals; reductions are deferred into the
// consumer kernel's A-tile load — no atomics, no epilogue passes).
__device__ float g_h1p[4 * BDIM * H1D];    // GEMM1 partials (split-K=4)
__device__ float g_h2p[8 * BDIM * H2D];    // GEMM2 partials (split-K=8)
__device__ float g_Mp [4 * BDIM * NMD];    // GEMM3 partials (split-K=4)
__device__ float g_obp[4 * OUTD * BDIM];   // pairwise partials [split][o][j]
__device__ float g_z3p[6 * BDIM * OUTD];   // GEMM4 partials (4 h2-chunks + 2 ob-chunks)

__device__ __forceinline__ float lrelu(float v) { return fmaxf(v, 0.2f * v); }

// ---------------------------------------------------------------------------
// SIMT GEMM, 64x64 tile, 64 threads, 8x8 micro-tile (split 4+4 rows/cols to
// keep LDS conflict-free), BK=16, split-K via blockIdx.z.
// A-load fuses: sum of NPART split-K partials (stride apStride) and, if ACT,
// +bias[k] then leaky-relu. If OB, A is the k-major ob-partial layout
// [k][m] (ld=512): sum NPART partials then subtract 1 (no transpose needed).
// ---------------------------------------------------------------------------
template<int NPART, int ACT, int OB>
__global__ __launch_bounds__(64)
void gemm_k(const float* __restrict__ Abase, int apStride,
            const float* __restrict__ bias,
            const float* __restrict__ Bm,
            float* __restrict__ Cpart, int cpStride,
            int Kc, int lda, int ldb, int ldc)
{
    __shared__ float As[16][68];
    __shared__ float Bs[16][68];

    const int tid  = threadIdx.x;
    const int tn   = (tid & 7) * 4;   // cols tn..tn+3 and tn+32..tn+35
    const int tm   = (tid >> 3) * 4;  // rows tm..tm+3 and tm+32..tm+35
    const int row0 = blockIdx.y * 64;
    const int col0 = blockIdx.x * 64;
    const int k0   = blockIdx.z * Kc;

    float acc[8][8] = {};

    for (int kt = 0; kt < Kc; kt += 16) {
        const int kbase = k0 + kt;

        if (!OB) {
            // A tile: 64 rows x 16 k, LDG float4 along k, transpose into As[k][m]
            #pragma unroll
            for (int i = 0; i < 4; i++) {
                int f  = tid + i * 64;
                int r  = f >> 2;
                int kq = (f & 3) * 4;
                const float* ap = Abase + (size_t)(row0 + r) * lda + kbase + kq;
                float4 v = *(const float4*)ap;
                #pragma unroll
                for (int p = 1; p < NPART; p++) {
                    float4 u = *(const float4*)(ap + (size_t)p * apStride);
                    v.x += u.x; v.y += u.y; v.z += u.z; v.w += u.w;
                }
                if (ACT) {
                    float4 bv = *(const float4*)(bias + kbase + kq);
                    v.x = lrelu(v.x + bv.x);
                    v.y = lrelu(v.y + bv.y);
                    v.z = lrelu(v.z + bv.z);
                    v.w = lrelu(v.w + bv.w);
                }
                As[kq + 0][r] = v.x;
                As[kq + 1][r] = v.y;
                As[kq + 2][r] = v.z;
                As[kq + 3][r] = v.w;
            }
        } else {
            // ob layout is already k-major [k][m] (ld = BDIM): straight copy
            #pragma unroll
            for (int i = 0; i < 4; i++) {
                int f  = tid + i * 64;
                int kk = f >> 4;
                int mq = (f & 15) * 4;
                const float* ap = Abase + (size_t)(kbase + kk) * BDIM + row0 + mq;
                float4 v = *(const float4*)ap;
                #pragma unroll
                for (int p = 1; p < NPART; p++) {
                    float4 u = *(const float4*)(ap + (size_t)p * apStride);
                    v.x += u.x; v.y += u.y; v.z += u.z; v.w += u.w;
                }
                v.x -= 1.0f; v.y -= 1.0f; v.z -= 1.0f; v.w -= 1.0f;
                *(float4*)&As[kk][mq] = v;
            }
        }

        // B tile: 16 k x 64 n, coalesced float4 along n
        #pragma unroll
        for (int i = 0; i < 4; i++) {
            int f  = tid + i * 64;
            int kk = f >> 4;
            int nq = (f & 15) * 4;
            *(float4*)&Bs[kk][nq] =
                *(const float4*)(Bm + (size_t)(kbase + kk) * ldb + col0 + nq);
        }
        __syncthreads();

        #pragma unroll
        for (int kk = 0; kk < 16; kk++) {
            float4 a0 = *(const float4*)&As[kk][tm];
            float4 a1 = *(const float4*)&As[kk][tm + 32];
            float4 b0 = *(const float4*)&Bs[kk][tn];
            float4 b1 = *(const float4*)&Bs[kk][tn + 32];
            float a[8] = {a0.x, a0.y, a0.z, a0.w, a1.x, a1.y, a1.z, a1.w};
            float b[8] = {b0.x, b0.y, b0.z, b0.w, b1.x, b1.y, b1.z, b1.w};
            #pragma unroll
            for (int mi = 0; mi < 8; mi++)
                #pragma unroll
                for (int ni = 0; ni < 8; ni++)
                    acc[mi][ni] += a[mi] * b[ni];
        }
        __syncthreads();
    }

    float* cp = Cpart + (size_t)blockIdx.z * cpStride;
    #pragma unroll
    for (int mi = 0; mi < 8; mi++) {
        int row = row0 + tm + (mi < 4 ? mi : 28 + mi);
        float4 v0 = make_float4(acc[mi][0], acc[mi][1], acc[mi][2], acc[mi][3]);
        float4 v1 = make_float4(acc[mi][4], acc[mi][5], acc[mi][6], acc[mi][7]);
        *(float4*)&cp[(size_t)row * ldc + col0 + tn]      = v0;
        *(float4*)&cp[(size_t)row * ldc + col0 + tn + 32] = v1;
    }
}

// ---------------------------------------------------------------------------
// Pairwise minibatch discrimination, split over i into 4 chunks of 128.
// grid (o=128, split=4), 512 threads (one per j).
// M is materialized as 4 split-K partials (stride MS); we sum + pre-scale by
// log2e at load so the inner loop uses EX2 directly.
// Output partial [split][o][j] (coalesced over j); consumer sums 4 and -1.
// ---------------------------------------------------------------------------
__global__ __launch_bounds__(512)
void pairwise_k(const float* __restrict__ Mp, float* __restrict__ obp)
{
    __shared__ float s[128 * 8];
    const int o  = blockIdx.x;
    const int sp = blockIdx.y;
    const int j  = threadIdx.x;
    const int i0 = sp * 128;
    const size_t MS = (size_t)BDIM * NMD;

    for (int idx = j; idx < 128 * KDD; idx += 512) {
        int i = idx / KDD, k = idx - i * KDD;
        const float* p = Mp + (size_t)(i0 + i) * NMD + o * KDD + k;
        s[i * 8 + k] = (p[0] + p[MS] + p[2 * MS] + p[3 * MS]) * LOG2E;
    }
    const float* pj = Mp + (size_t)j * NMD + o * KDD;
    float mj[KDD];
    #pragma unroll
    for (int k = 0; k < KDD; k++)
        mj[k] = (pj[k] + pj[k + MS] + pj[k + 2 * MS] + pj[k + 3 * MS]) * LOG2E;
    __syncthreads();

    float acc0 = 0.f, acc1 = 0.f;
    #pragma unroll 8
    for (int i = 0; i < 128; i++) {
        float4 v = *(const float4*)&s[i * 8];
        float  w = s[i * 8 + 4];
        float n = fabsf(v.x - mj[0]) + fabsf(v.y - mj[1]) + fabsf(v.z - mj[2])
                + fabsf(v.w - mj[3]) + fabsf(w - mj[4]);
        float e;
        asm("ex2.approx.f32 %0, %1;" : "=f"(e) : "f"(-n));
        if (i & 1) acc1 += e; else acc0 += e;
    }
    obp[(size_t)sp * (OUTD * BDIM) + o * BDIM + j] = acc0 + acc1;
}

// ---------------------------------------------------------------------------
// Final: z3 = lrelu(sum of 6 GEMM4 partials + b3); out = z3 @ W4 + b4.
// One warp per batch row.
// ---------------------------------------------------------------------------
__global__ __launch_bounds__(256)
void final_k(const float* __restrict__ z3p, const float* __restrict__ b3,
             const float* __restrict__ W4, const float* __restrict__ b4,
             float* __restrict__ out)
{
    const size_t ZS = (size_t)BDIM * OUTD;
    int gw   = (blockIdx.x * 256 + threadIdx.x) >> 5;
    int lane = threadIdx.x & 31;
    float sum = 0.f;
    #pragma unroll
    for (int it = 0; it < 4; it++) {
        int k = it * 32 + lane;
        const float* p = z3p + (size_t)gw * OUTD + k;
        float v = ((p[0] + p[ZS]) + (p[2 * ZS] + p[3 * ZS]))
                + (p[4 * ZS] + p[5 * ZS]) + b3[k];
        v = lrelu(v);
        sum += v * W4[k];
    }
    #pragma unroll
    for (int off = 16; off; off >>= 1)
        sum += __shfl_xor_sync(0xffffffffu, sum, off);
    if (lane == 0) out[gw] = sum + b4[0];
}

// ---------------------------------------------------------------------------
extern "C" void kernel_launch(void* const* d_in, const int* in_sizes, int n_in,
                              void* d_out, int out_size)
{
    (void)in_sizes; (void)n_in; (void)out_size;
    const float* x  = (const float*)d_in[0];
    const float* W1 = (const float*)d_in[1];
    const float* b1 = (const float*)d_in[2];
    const float* W2 = (const float*)d_in[3];
    const float* b2 = (const float*)d_in[4];
    const float* T  = (const float*)d_in[5];
    const float* W3 = (const float*)d_in[6];
    const float* b3 = (const float*)d_in[7];
    const float* W4 = (const float*)d_in[8];
    const float* b4 = (const float*)d_in[9];
    float* out = (float*)d_out;

    float *h1p, *h2p, *Mp, *obp, *z3p;
    cudaGetSymbolAddress((void**)&h1p, g_h1p);
    cudaGetSymbolAddress((void**)&h2p, g_h2p);
    cudaGetSymbolAddress((void**)&Mp,  g_Mp);
    cudaGetSymbolAddress((void**)&obp, g_obp);
    cudaGetSymbolAddress((void**)&z3p, g_z3p);

    // GEMM1: h1 = x @ W1, split-K=4 (K=1024 -> Kc=256), 256 blocks
    gemm_k<1,0,0><<<dim3(8,8,4), 64>>>(x, 0, nullptr, W1,
                                       h1p, BDIM*H1D, 256, FDIM, H1D, H1D);
    // GEMM2: h2 = lrelu(h1+b1) @ W2, split-K=8 (K=512 -> Kc=64), 256 blocks
    gemm_k<4,1,0><<<dim3(4,8,8), 64>>>(h1p, BDIM*H1D, b1, W2,
                                       h2p, BDIM*H2D, 64, H1D, H2D, H2D);
    // GEMM3: M = lrelu(h2+b2) @ T, split-K=4 (K=256 -> Kc=64), 320 blocks
    gemm_k<8,1,0><<<dim3(10,8,4), 64>>>(h2p, BDIM*H2D, b2, T,
                                        Mp, BDIM*NMD, 64, H2D, NMD, NMD);
    // GEMM4a: z3 += lrelu(h2+b2) @ W3[:256], split-K=4 (Kc=64), 64 blocks
    gemm_k<8,1,0><<<dim3(2,8,4), 64>>>(h2p, BDIM*H2D, b2, W3,
                                       z3p, BDIM*OUTD, 64, H2D, OUTD, OUTD);
    // Pairwise: o_b partials, grid (128 o, 4 i-chunks)
    pairwise_k<<<dim3(OUTD, 4), BDIM>>>(Mp, obp);
    // GEMM4b: z3 += (sum ob partials - 1) @ W3[256:], split-K=2 (Kc=64), 32 blocks
    gemm_k<4,0,1><<<dim3(2,8,2), 64>>>(obp, OUTD*BDIM, nullptr, W3 + 256*OUTD,
                                       z3p + 4*(size_t)BDIM*OUTD, BDIM*OUTD,
                                       64, 0, OUTD, OUTD);
    // Final: lrelu(sum z3 partials + b3) @ W4 + b4
    final_k<<<64, 256>>>(z3p, b3, W4, b4, out);
}

// round 4
// speedup vs baseline: 1.3036x; 1.1926x over previous
#include <cuda_runtime.h>

#define BDIM 512
#define FDIM 1024
#define H1D  512
#define H2D  256
#define OUTD 128
#define KDD  5
#define NMD  (OUTD*KDD)   // 640
#define LOG2E 1.44269504f

// Split-K partial buffers; reductions are deferred into the consumer's A-load.
__device__ float g_h1p[4 * BDIM * H1D];    // GEMM1 partials (split-K=4)
__device__ float g_h2p[4 * BDIM * H2D];    // GEMM2 partials (split-K=4)
__device__ float g_Mp [2 * BDIM * NMD];    // GEMM3 partials (split-K=2)
__device__ float g_obp[4 * OUTD * BDIM];   // pairwise partials [split][o][j]
__device__ float g_z3p[6 * BDIM * OUTD];   // GEMM4 partials (4 h2 + 2 ob)

__device__ __forceinline__ float lrelu(float v) { return fmaxf(v, 0.2f * v); }

#define FMA2(c, a, b) asm("fma.rn.f32x2 %0, %1, %2, %0;" : "+l"(c) : "l"(a), "l"(b))
#define SPLAT(d, x)   asm("mov.b64 %0, {%1, %1};" : "=l"(d) : "f"(x))

// ---------------------------------------------------------------------------
// SIMT GEMM, 128 threads (4 warps), tile 128(M) x 64(N), BK=16, 8x8 microtile.
// Inner loop uses packed f32x2 FMA: accumulators hold adjacent-n pairs, so
// per thread per kk: 2 LDS.128 (a), 2 LDS.128 (b pairs), 8 splats, 32 FFMA2.
// A-load fuses the sum of NPART split-K partials and optional bias+leaky-relu.
// OB=1: A is the k-major [k][m] pairwise-partial layout (ld=512), sum then -1.
// ---------------------------------------------------------------------------
template<int NPART, int ACT, int OB>
__global__ __launch_bounds__(128)
void gemm_k(const float* __restrict__ Abase, int apStride,
            const float* __restrict__ bias,
            const float* __restrict__ Bm,
            float* __restrict__ Cpart, int cpStride,
            int Kc, int lda, int ldb, int ldc)
{
    __shared__ float As[16][132];   // [k][m], stride keeps 16B alignment
    __shared__ float Bs[16][68];    // [k][n]

    const int tid  = threadIdx.x;
    const int tn   = (tid & 7) * 4;    // cols tn..tn+3 and tn+32..tn+35
    const int tm   = (tid >> 3) * 4;   // rows tm..tm+3 and tm+64..tm+67
    const int row0 = blockIdx.y * 128;
    const int col0 = blockIdx.x * 64;
    const int k0   = blockIdx.z * Kc;

    unsigned long long acc[8][4] = {};   // packed pairs over n

    for (int kt = 0; kt < Kc; kt += 16) {
        const int kbase = k0 + kt;

        if (!OB) {
            // A tile: 128 rows x 16 k, float4 LDG along k, transpose to As[k][m]
            #pragma unroll
            for (int i = 0; i < 4; i++) {
                int f  = tid + i * 128;
                int r  = f >> 2;
                int kq = (f & 3) * 4;
                const float* ap = Abase + (size_t)(row0 + r) * lda + kbase + kq;
                float4 v = *(const float4*)ap;
                #pragma unroll
                for (int p = 1; p < NPART; p++) {
                    float4 u = *(const float4*)(ap + (size_t)p * apStride);
                    v.x += u.x; v.y += u.y; v.z += u.z; v.w += u.w;
                }
                if (ACT) {
                    float4 bv = *(const float4*)(bias + kbase + kq);
                    v.x = lrelu(v.x + bv.x);
                    v.y = lrelu(v.y + bv.y);
                    v.z = lrelu(v.z + bv.z);
                    v.w = lrelu(v.w + bv.w);
                }
                As[kq + 0][r] = v.x;
                As[kq + 1][r] = v.y;
                As[kq + 2][r] = v.z;
                As[kq + 3][r] = v.w;
            }
        } else {
            // k-major [k][m] layout (ld = BDIM): straight float4 copy
            #pragma unroll
            for (int i = 0; i < 4; i++) {
                int f  = tid + i * 128;
                int kk = f >> 5;
                int mq = (f & 31) * 4;
                const float* ap = Abase + (size_t)(kbase + kk) * BDIM + row0 + mq;
                float4 v = *(const float4*)ap;
                #pragma unroll
                for (int p = 1; p < NPART; p++) {
                    float4 u = *(const float4*)(ap + (size_t)p * apStride);
                    v.x += u.x; v.y += u.y; v.z += u.z; v.w += u.w;
                }
                v.x -= 1.0f; v.y -= 1.0f; v.z -= 1.0f; v.w -= 1.0f;
                *(float4*)&As[kk][mq] = v;
            }
        }

        // B tile: 16 k x 64 n, coalesced float4
        #pragma unroll
        for (int i = 0; i < 2; i++) {
            int f  = tid + i * 128;
            int kk = f >> 4;
            int nq = (f & 15) * 4;
            *(float4*)&Bs[kk][nq] =
                *(const float4*)(Bm + (size_t)(kbase + kk) * ldb + col0 + nq);
        }
        __syncthreads();

        #pragma unroll
        for (int kk = 0; kk < 16; kk++) {
            float4 a0 = *(const float4*)&As[kk][tm];
            float4 a1 = *(const float4*)&As[kk][tm + 64];
            ulonglong2 bp0 = *(const ulonglong2*)&Bs[kk][tn];
            ulonglong2 bp1 = *(const ulonglong2*)&Bs[kk][tn + 32];
            unsigned long long bp[4] = {bp0.x, bp0.y, bp1.x, bp1.y};
            float av[8] = {a0.x, a0.y, a0.z, a0.w, a1.x, a1.y, a1.z, a1.w};
            unsigned long long as_[8];
            #pragma unroll
            for (int mi = 0; mi < 8; mi++) SPLAT(as_[mi], av[mi]);
            #pragma unroll
            for (int mi = 0; mi < 8; mi++)
                #pragma unroll
                for (int nj = 0; nj < 4; nj++)
                    FMA2(acc[mi][nj], as_[mi], bp[nj]);
        }
        __syncthreads();
    }

    // Epilogue: packed accumulators store directly as 16B stores
    float* cp = Cpart + (size_t)blockIdx.z * cpStride;
    #pragma unroll
    for (int mi = 0; mi < 8; mi++) {
        int row = row0 + tm + (mi < 4 ? mi : 60 + mi);
        ulonglong2 v0, v1;
        v0.x = acc[mi][0]; v0.y = acc[mi][1];
        v1.x = acc[mi][2]; v1.y = acc[mi][3];
        *(ulonglong2*)&cp[(size_t)row * ldc + col0 + tn]      = v0;
        *(ulonglong2*)&cp[(size_t)row * ldc + col0 + tn + 32] = v1;
    }
}

// ---------------------------------------------------------------------------
// Pairwise minibatch discrimination, split over i into 4 chunks of 128.
// grid (o=128, split=4), 512 threads (one per j). Sums 2 M split-K partials
// at load and pre-scales by log2e so the inner loop is pure EX2.
// ---------------------------------------------------------------------------
__global__ __launch_bounds__(512)
void pairwise_k(const float* __restrict__ Mp, float* __restrict__ obp)
{
    __shared__ float s[128 * 8];
    const int o  = blockIdx.x;
    const int sp = blockIdx.y;
    const int j  = threadIdx.x;
    const int i0 = sp * 128;
    const size_t MS = (size_t)BDIM * NMD;

    for (int idx = j; idx < 128 * KDD; idx += 512) {
        int i = idx / KDD, k = idx - i * KDD;
        const float* p = Mp + (size_t)(i0 + i) * NMD + o * KDD + k;
        s[i * 8 + k] = (p[0] + p[MS]) * LOG2E;
    }
    const float* pj = Mp + (size_t)j * NMD + o * KDD;
    float mj[KDD];
    #pragma unroll
    for (int k = 0; k < KDD; k++)
        mj[k] = (pj[k] + pj[k + MS]) * LOG2E;
    __syncthreads();

    float acc0 = 0.f, acc1 = 0.f;
    #pragma unroll 8
    for (int i = 0; i < 128; i++) {
        float4 v = *(const float4*)&s[i * 8];
        float  w = s[i * 8 + 4];
        float n = fabsf(v.x - mj[0]) + fabsf(v.y - mj[1]) + fabsf(v.z - mj[2])
                + fabsf(v.w - mj[3]) + fabsf(w - mj[4]);
        float e;
        asm("ex2.approx.f32 %0, %1;" : "=f"(e) : "f"(-n));
        if (i & 1) acc1 += e; else acc0 += e;
    }
    obp[(size_t)sp * (OUTD * BDIM) + o * BDIM + j] = acc0 + acc1;
}

// ---------------------------------------------------------------------------
// Final: z3 = lrelu(sum of 6 GEMM4 partials + b3); out = z3 @ W4 + b4.
// ---------------------------------------------------------------------------
__global__ __launch_bounds__(256)
void final_k(const float* __restrict__ z3p, const float* __restrict__ b3,
             const float* __restrict__ W4, const float* __restrict__ b4,
             float* __restrict__ out)
{
    const size_t ZS = (size_t)BDIM * OUTD;
    int gw   = (blockIdx.x * 256 + threadIdx.x) >> 5;
    int lane = threadIdx.x & 31;
    float sum = 0.f;
    #pragma unroll
    for (int it = 0; it < 4; it++) {
        int k = it * 32 + lane;
        const float* p = z3p + (size_t)gw * OUTD + k;
        float v = ((p[0] + p[ZS]) + (p[2 * ZS] + p[3 * ZS]))
                + (p[4 * ZS] + p[5 * ZS]) + b3[k];
        v = lrelu(v);
        sum += v * W4[k];
    }
    #pragma unroll
    for (int off = 16; off; off >>= 1)
        sum += __shfl_xor_sync(0xffffffffu, sum, off);
    if (lane == 0) out[gw] = sum + b4[0];
}

// ---------------------------------------------------------------------------
extern "C" void kernel_launch(void* const* d_in, const int* in_sizes, int n_in,
                              void* d_out, int out_size)
{
    (void)in_sizes; (void)n_in; (void)out_size;
    const float* x  = (const float*)d_in[0];
    const float* W1 = (const float*)d_in[1];
    const float* b1 = (const float*)d_in[2];
    const float* W2 = (const float*)d_in[3];
    const float* b2 = (const float*)d_in[4];
    const float* T  = (const float*)d_in[5];
    const float* W3 = (const float*)d_in[6];
    const float* b3 = (const float*)d_in[7];
    const float* W4 = (const float*)d_in[8];
    const float* b4 = (const float*)d_in[9];
    float* out = (float*)d_out;

    float *h1p, *h2p, *Mp, *obp, *z3p;
    cudaGetSymbolAddress((void**)&h1p, g_h1p);
    cudaGetSymbolAddress((void**)&h2p, g_h2p);
    cudaGetSymbolAddress((void**)&Mp,  g_Mp);
    cudaGetSymbolAddress((void**)&obp, g_obp);
    cudaGetSymbolAddress((void**)&z3p, g_z3p);

    // GEMM1: h1 = x @ W1, split-K=4 (Kc=256) -> 4x8x4 = 128 blocks
    gemm_k<1,0,0><<<dim3(8,4,4), 128>>>(x, 0, nullptr, W1,
                                        h1p, BDIM*H1D, 256, FDIM, H1D, H1D);
    // GEMM2: h2 = lrelu(h1+b1) @ W2, split-K=4 (Kc=128) -> 64 blocks
    gemm_k<4,1,0><<<dim3(4,4,4), 128>>>(h1p, BDIM*H1D, b1, W2,
                                        h2p, BDIM*H2D, 128, H1D, H2D, H2D);
    // GEMM4a: z3 partials = lrelu(h2+b2) @ W3[:256], split-K=4 (Kc=64) -> 32 blocks
    gemm_k<4,1,0><<<dim3(2,4,4), 128>>>(h2p, BDIM*H2D, b2, W3,
                                        z3p, BDIM*OUTD, 64, H2D, OUTD, OUTD);
    // GEMM3: M = lrelu(h2+b2) @ T, split-K=2 (Kc=128) -> 80 blocks
    gemm_k<4,1,0><<<dim3(10,4,2), 128>>>(h2p, BDIM*H2D, b2, T,
                                         Mp, BDIM*NMD, 128, H2D, NMD, NMD);
    // Pairwise: o_b partials, grid (128 o, 4 i-chunks) = 512 blocks
    pairwise_k<<<dim3(OUTD, 4), BDIM>>>(Mp, obp);
    // GEMM4b: z3 partials += (sum ob partials - 1) @ W3[256:], split-K=2 -> 16 blocks
    gemm_k<4,0,1><<<dim3(2,4,2), 128>>>(obp, OUTD*BDIM, nullptr, W3 + 256*OUTD,
                                        z3p + 4*(size_t)BDIM*OUTD, BDIM*OUTD,
                                        64, 0, OUTD, OUTD);
    // Final: lrelu(sum z3 partials + b3) @ W4 + b4
    final_k<<<64, 256>>>(z3p, b3, W4, b4, out);
}

// round 5
// speedup vs baseline: 1.3576x; 1.0415x over previous
#include <cuda_runtime.h>

#define BDIM 512
#define FDIM 1024
#define H1D  512
#define H2D  256
#define OUTD 128
#define KDD  5
#define NMD  (OUTD*KDD)   // 640
#define LOG2E 1.44269504f

// Split-K partial buffers; reductions are deferred into the consumer's A-load.
__device__ float g_h1p[4 * BDIM * H1D];    // GEMM1 partials (split-K=4)
__device__ float g_h2p[8 * BDIM * H2D];    // GEMM2 partials (split-K=8)
__device__ float g_Mp [2 * BDIM * NMD];    // GEMM3 partials (split-K=2)
__device__ float g_obp[4 * OUTD * BDIM];   // pairwise partials [split][o][j]
__device__ float g_z3p[6 * BDIM * OUTD];   // GEMM4 partials (4 h2 + 2 ob)

__device__ __forceinline__ float lrelu(float v) { return fmaxf(v, 0.2f * v); }

#define FMA2(c, a, b) asm("fma.rn.f32x2 %0, %1, %2, %0;" : "+l"(c) : "l"(a), "l"(b))
#define SPLAT(d, x)   asm("mov.b64 %0, {%1, %1};" : "=l"(d) : "f"(x))

// ---------------------------------------------------------------------------
// SIMT GEMM, 64x64 tile, 128 threads (4 warps), BK=16, 4(m)x8(n) microtile in
// packed f32x2 (16 FFMA2/kk/thread -> fma-pipe balanced at peak).
// Small tiles => 2x block count => 4+ blocks/SM co-resident for latency hiding.
// Double-buffered smem with register prefetch: LDG for tile t+1 issues before
// the 16-kk compute of tile t; single __syncthreads per k-tile.
// A-load fuses the sum of NPART split-K partials and optional bias+leaky-relu.
// OB=1: A is the k-major [k][m] pairwise-partial layout (ld=512), sum then -1.
// ---------------------------------------------------------------------------
template<int NPART, int ACT, int OB>
__global__ __launch_bounds__(128)
void gemm_k(const float* __restrict__ Abase, int apStride,
            const float* __restrict__ bias,
            const float* __restrict__ Bm,
            float* __restrict__ Cpart, int cpStride,
            int Kc, int lda, int ldb, int ldc)
{
    __shared__ float As[2][16][68];   // [buf][k][m]
    __shared__ float Bs[2][16][68];   // [buf][k][n]

    const int tid  = threadIdx.x;
    const int tn   = (tid & 7) * 8;   // 8 contiguous cols
    const int tm   = (tid >> 3) * 4;  // 4 contiguous rows
    const int row0 = blockIdx.y * 64;
    const int col0 = blockIdx.x * 64;
    const int k0   = blockIdx.z * Kc;

    float4 pa[2], pb[2];              // prefetch registers

    auto fetch = [&](int kbase) {
        #pragma unroll
        for (int i = 0; i < 2; i++) {
            int f = tid + i * 128;
            if (!OB) {
                int r = f >> 2, kq = (f & 3) * 4;
                const float* ap = Abase + (size_t)(row0 + r) * lda + kbase + kq;
                float4 v = *(const float4*)ap;
                #pragma unroll
                for (int p = 1; p < NPART; p++) {
                    float4 u = *(const float4*)(ap + (size_t)p * apStride);
                    v.x += u.x; v.y += u.y; v.z += u.z; v.w += u.w;
                }
                if (ACT) {
                    float4 bv = *(const float4*)(bias + kbase + kq);
                    v.x = lrelu(v.x + bv.x);
                    v.y = lrelu(v.y + bv.y);
                    v.z = lrelu(v.z + bv.z);
                    v.w = lrelu(v.w + bv.w);
                }
                pa[i] = v;
            } else {
                int kk = f >> 4, mq = (f & 15) * 4;
                const float* ap = Abase + (size_t)(kbase + kk) * BDIM + row0 + mq;
                float4 v = *(const float4*)ap;
                #pragma unroll
                for (int p = 1; p < NPART; p++) {
                    float4 u = *(const float4*)(ap + (size_t)p * apStride);
                    v.x += u.x; v.y += u.y; v.z += u.z; v.w += u.w;
                }
                v.x -= 1.0f; v.y -= 1.0f; v.z -= 1.0f; v.w -= 1.0f;
                pa[i] = v;
            }
            int kk = f >> 4, nq = (f & 15) * 4;
            pb[i] = *(const float4*)(Bm + (size_t)(kbase + kk) * ldb + col0 + nq);
        }
    };
    auto stick = [&](int buf) {
        #pragma unroll
        for (int i = 0; i < 2; i++) {
            int f = tid + i * 128;
            if (!OB) {
                int r = f >> 2, kq = (f & 3) * 4;
                As[buf][kq + 0][r] = pa[i].x;
                As[buf][kq + 1][r] = pa[i].y;
                As[buf][kq + 2][r] = pa[i].z;
                As[buf][kq + 3][r] = pa[i].w;
            } else {
                int kk = f >> 4, mq = (f & 15) * 4;
                *(float4*)&As[buf][kk][mq] = pa[i];
            }
            int kk = f >> 4, nq = (f & 15) * 4;
            *(float4*)&Bs[buf][kk][nq] = pb[i];
        }
    };

    unsigned long long acc[4][4] = {};   // [m][n-pair]

    fetch(k0);
    stick(0);
    __syncthreads();

    for (int kt = 0; kt < Kc; kt += 16) {
        const int  cur = (kt >> 4) & 1;
        const bool nxt = (kt + 16) < Kc;
        if (nxt) fetch(k0 + kt + 16);

        #pragma unroll
        for (int kk = 0; kk < 16; kk++) {
            float4 a = *(const float4*)&As[cur][kk][tm];
            ulonglong2 b0 = *(const ulonglong2*)&Bs[cur][kk][tn];
            ulonglong2 b1 = *(const ulonglong2*)&Bs[cur][kk][tn + 4];
            unsigned long long bp[4] = {b0.x, b0.y, b1.x, b1.y};
            float av[4] = {a.x, a.y, a.z, a.w};
            unsigned long long as_[4];
            #pragma unroll
            for (int mi = 0; mi < 4; mi++) SPLAT(as_[mi], av[mi]);
            #pragma unroll
            for (int mi = 0; mi < 4; mi++)
                #pragma unroll
                for (int nj = 0; nj < 4; nj++)
                    FMA2(acc[mi][nj], as_[mi], bp[nj]);
        }
        if (nxt) stick(cur ^ 1);
        __syncthreads();
    }

    float* cp = Cpart + (size_t)blockIdx.z * cpStride;
    #pragma unroll
    for (int mi = 0; mi < 4; mi++) {
        int row = row0 + tm + mi;
        ulonglong2 v0, v1;
        v0.x = acc[mi][0]; v0.y = acc[mi][1];
        v1.x = acc[mi][2]; v1.y = acc[mi][3];
        *(ulonglong2*)&cp[(size_t)row * ldc + col0 + tn]     = v0;
        *(ulonglong2*)&cp[(size_t)row * ldc + col0 + tn + 4] = v1;
    }
}

// ---------------------------------------------------------------------------
// Pairwise minibatch discrimination, split over i into 4 chunks of 128.
// grid (o=128, split=4), 512 threads (one per j). Sums 2 M split-K partials
// at load and pre-scales by log2e so the inner loop is pure EX2.
// ---------------------------------------------------------------------------
__global__ __launch_bounds__(512)
void pairwise_k(const float* __restrict__ Mp, float* __restrict__ obp)
{
    __shared__ float s[128 * 8];
    const int o  = blockIdx.x;
    const int sp = blockIdx.y;
    const int j  = threadIdx.x;
    const int i0 = sp * 128;
    const size_t MS = (size_t)BDIM * NMD;

    for (int idx = j; idx < 128 * KDD; idx += 512) {
        int i = idx / KDD, k = idx - i * KDD;
        const float* p = Mp + (size_t)(i0 + i) * NMD + o * KDD + k;
        s[i * 8 + k] = (p[0] + p[MS]) * LOG2E;
    }
    const float* pj = Mp + (size_t)j * NMD + o * KDD;
    float mj[KDD];
    #pragma unroll
    for (int k = 0; k < KDD; k++)
        mj[k] = (pj[k] + pj[k + MS]) * LOG2E;
    __syncthreads();

    float acc0 = 0.f, acc1 = 0.f;
    #pragma unroll 16
    for (int i = 0; i < 128; i++) {
        float4 v = *(const float4*)&s[i * 8];
        float  w = s[i * 8 + 4];
        float n = fabsf(v.x - mj[0]) + fabsf(v.y - mj[1]) + fabsf(v.z - mj[2])
                + fabsf(v.w - mj[3]) + fabsf(w - mj[4]);
        float e;
        asm("ex2.approx.f32 %0, %1;" : "=f"(e) : "f"(-n));
        if (i & 1) acc1 += e; else acc0 += e;
    }
    obp[(size_t)sp * (OUTD * BDIM) + o * BDIM + j] = acc0 + acc1;
}

// ---------------------------------------------------------------------------
// Final: z3 = lrelu(sum of 6 GEMM4 partials + b3); out = z3 @ W4 + b4.
// ---------------------------------------------------------------------------
__global__ __launch_bounds__(256)
void final_k(const float* __restrict__ z3p, const float* __restrict__ b3,
             const float* __restrict__ W4, const float* __restrict__ b4,
             float* __restrict__ out)
{
    const size_t ZS = (size_t)BDIM * OUTD;
    int gw   = (blockIdx.x * 256 + threadIdx.x) >> 5;
    int lane = threadIdx.x & 31;
    float sum = 0.f;
    #pragma unroll
    for (int it = 0; it < 4; it++) {
        int k = it * 32 + lane;
        const float* p = z3p + (size_t)gw * OUTD + k;
        float v = ((p[0] + p[ZS]) + (p[2 * ZS] + p[3 * ZS]))
                + (p[4 * ZS] + p[5 * ZS]) + b3[k];
        v = lrelu(v);
        sum += v * W4[k];
    }
    #pragma unroll
    for (int off = 16; off; off >>= 1)
        sum += __shfl_xor_sync(0xffffffffu, sum, off);
    if (lane == 0) out[gw] = sum + b4[0];
}

// ---------------------------------------------------------------------------
extern "C" void kernel_launch(void* const* d_in, const int* in_sizes, int n_in,
                              void* d_out, int out_size)
{
    (void)in_sizes; (void)n_in; (void)out_size;
    const float* x  = (const float*)d_in[0];
    const float* W1 = (const float*)d_in[1];
    const float* b1 = (const float*)d_in[2];
    const float* W2 = (const float*)d_in[3];
    const float* b2 = (const float*)d_in[4];
    const float* T  = (const float*)d_in[5];
    const float* W3 = (const float*)d_in[6];
    const float* b3 = (const float*)d_in[7];
    const float* W4 = (const float*)d_in[8];
    const float* b4 = (const float*)d_in[9];
    float* out = (float*)d_out;

    float *h1p, *h2p, *Mp, *obp, *z3p;
    cudaGetSymbolAddress((void**)&h1p, g_h1p);
    cudaGetSymbolAddress((void**)&h2p, g_h2p);
    cudaGetSymbolAddress((void**)&Mp,  g_Mp);
    cudaGetSymbolAddress((void**)&obp, g_obp);
    cudaGetSymbolAddress((void**)&z3p, g_z3p);

    // GEMM1: h1 = x @ W1, split-K=4 (Kc=256) -> 8x8x4 = 256 blocks
    gemm_k<1,0,0><<<dim3(8,8,4), 128>>>(x, 0, nullptr, W1,
                                        h1p, BDIM*H1D, 256, FDIM, H1D, H1D);
    // GEMM2: h2 = lrelu(h1+b1) @ W2, split-K=8 (Kc=64) -> 4x8x8 = 256 blocks
    gemm_k<4,1,0><<<dim3(4,8,8), 128>>>(h1p, BDIM*H1D, b1, W2,
                                        h2p, BDIM*H2D, 64, H1D, H2D, H2D);
    // GEMM4a: z3 partials = lrelu(h2+b2) @ W3[:256], split-K=4 (Kc=64) -> 64 blocks
    gemm_k<8,1,0><<<dim3(2,8,4), 128>>>(h2p, BDIM*H2D, b2, W3,
                                        z3p, BDIM*OUTD, 64, H2D, OUTD, OUTD);
    // GEMM3: M = lrelu(h2+b2) @ T, split-K=2 (Kc=128) -> 10x8x2 = 160 blocks
    gemm_k<8,1,0><<<dim3(10,8,2), 128>>>(h2p, BDIM*H2D, b2, T,
                                         Mp, BDIM*NMD, 128, H2D, NMD, NMD);
    // Pairwise: o_b partials, grid (128 o, 4 i-chunks) = 512 blocks
    pairwise_k<<<dim3(OUTD, 4), BDIM>>>(Mp, obp);
    // GEMM4b: z3 partials += (sum ob partials - 1) @ W3[256:], split-K=2 -> 32 blocks
    gemm_k<4,0,1><<<dim3(2,8,2), 128>>>(obp, OUTD*BDIM, nullptr, W3 + 256*OUTD,
                                        z3p + 4*(size_t)BDIM*OUTD, BDIM*OUTD,
                                        64, 0, OUTD, OUTD);
    // Final: lrelu(sum z3 partials + b3) @ W4 + b4
    final_k<<<64, 256>>>(z3p, b3, W4, b4, out);
}